// round 2
// baseline (speedup 1.0000x reference)
#include <cuda_runtime.h>

#define CIN 256
#define CK  8      // input-channel chunk per smem stage
#define PXT 128    // pixels per block tile
#define COT 64     // output channels per block tile

// Scratch ping-pong buffers (largest level: 16*256*64*64 floats = 64 MiB each)
__device__ float g_bufA[16UL * 256 * 64 * 64];
__device__ float g_bufB[16UL * 256 * 64 * 64];
// Fused box(4)+ctr(1) prediction weights/bias
__device__ float g_w5[5 * 256 * 9];
__device__ float g_b5[8];

__global__ void pack5_kernel(const float* __restrict__ wb, const float* __restrict__ bb,
                             const float* __restrict__ wc, const float* __restrict__ bc) {
    int i = blockIdx.x * blockDim.x + threadIdx.x;
    const int n4 = 4 * 256 * 9;
    const int n5 = 5 * 256 * 9;
    if (i < n4)        g_w5[i] = wb[i];
    else if (i < n5)   g_w5[i] = wc[i - n4];
    if (i < 4)         g_b5[i] = bb[i];
    else if (i == 4)   g_b5[4] = bc[0];
}

// 3x3 SAME conv, Cin=256, stride 1.
// Block: 256 threads -> 64 Cout x 128 pixels. Thread: 4 Cout x 8 pixels.
// TO_OUT=false : write NCHW to y (with optional ReLU)
// TO_OUT=true  : write flattened (B, 5376, 85) layout at (row_off, co_off)
template <bool RELU, bool TO_OUT>
__global__ __launch_bounds__(256)
void conv3x3_kernel(const float* __restrict__ x, const float* __restrict__ w,
                    const float* __restrict__ bias, float* __restrict__ y,
                    int Cout, int H, int Wd, int row_off, int co_off)
{
    const int HW = H * Wd;
    const int R  = PXT / Wd + 2;   // input rows needed (with halo)
    const int SW = Wd + 4;         // padded smem row stride (multiple of 4 floats)

    __shared__ __align__(16) float w_s[COT * 73];  // [co_local][ci*9+tap], odd stride
    __shared__ __align__(16) float x_s[2176];      // [ci][R][SW], max 8*4*68

    const int tid = threadIdx.x;
    const int pg  = tid & 15;   // pixel group 0..15 (8 px each)
    const int cg  = tid >> 4;   // cout group 0..15 (4 co each, stride 16)
    const int b   = blockIdx.z;
    const int P0      = blockIdx.x * PXT;
    const int co_base = blockIdx.y * COT;
    const int y0  = P0 / Wd;
    const int p_start = pg * 8;
    const int gyl = p_start / Wd;   // local row of this thread's pixel group
    const int gx0 = p_start % Wd;   // leftmost padded col needed by this group

    float acc[4][8];
#pragma unroll
    for (int i = 0; i < 4; i++)
#pragma unroll
        for (int j = 0; j < 8; j++) acc[i][j] = 0.f;

    const int xload_n = CK * R * (Wd + 2);
    const float* xb = x + (size_t)b * CIN * HW;

    for (int cic = 0; cic < CIN; cic += CK) {
        __syncthreads();
        // ---- stage weights: [co][ci][tap] gmem (coalesced) -> w_s[co][ci*9+tap]
        for (int idx = tid; idx < COT * CK * 9; idx += 256) {
            int co_l = idx / (CK * 9);
            int rem  = idx % (CK * 9);
            int ci   = rem / 9;
            int tap  = rem % 9;
            int co_g = co_base + co_l;
            float v  = 0.f;
            if (co_g < Cout) v = w[((size_t)co_g * CIN + cic + ci) * 9 + tap];
            w_s[co_l * 73 + ci * 9 + tap] = v;
        }
        // ---- stage input tile with halo + zero padding
        for (int idx = tid; idx < xload_n; idx += 256) {
            int ci  = idx / (R * (Wd + 2));
            int rem = idx % (R * (Wd + 2));
            int r   = rem / (Wd + 2);
            int c   = rem % (Wd + 2);
            int gy  = y0 - 1 + r;
            int gx  = c - 1;
            float v = 0.f;
            if (gy >= 0 && gy < H && gx >= 0 && gx < Wd)
                v = xb[(size_t)(cic + ci) * HW + gy * Wd + gx];
            x_s[(ci * R + r) * SW + c] = v;
        }
        __syncthreads();

#pragma unroll 1
        for (int ci = 0; ci < CK; ci++) {
            const float* xp = &x_s[ci * R * SW];
#pragma unroll
            for (int dy = 0; dy < 3; dy++) {
                const float* rp = &xp[(gyl + dy) * SW + gx0];
                float xr[10];
                float4 a0 = *(const float4*)(rp);
                float4 a1 = *(const float4*)(rp + 4);
                float2 a2 = *(const float2*)(rp + 8);
                xr[0] = a0.x; xr[1] = a0.y; xr[2] = a0.z; xr[3] = a0.w;
                xr[4] = a1.x; xr[5] = a1.y; xr[6] = a1.z; xr[7] = a1.w;
                xr[8] = a2.x; xr[9] = a2.y;
#pragma unroll
                for (int dx = 0; dx < 3; dx++) {
                    float wv[4];
#pragma unroll
                    for (int i = 0; i < 4; i++)
                        wv[i] = w_s[(cg + i * 16) * 73 + ci * 9 + dy * 3 + dx];
#pragma unroll
                    for (int i = 0; i < 4; i++)
#pragma unroll
                        for (int j = 0; j < 8; j++)
                            acc[i][j] = fmaf(wv[i], xr[dx + j], acc[i][j]);
                }
            }
        }
    }

    // ---- epilogue
#pragma unroll
    for (int i = 0; i < 4; i++) {
        int co = co_base + cg + i * 16;
        if (co >= Cout) continue;
        float bv = bias[co];
        float v[8];
#pragma unroll
        for (int j = 0; j < 8; j++) {
            float t = acc[i][j] + bv;
            if (RELU) t = fmaxf(t, 0.f);
            v[j] = t;
        }
        if (!TO_OUT) {
            float* yp = y + ((size_t)b * Cout + co) * HW + P0 + p_start;
            *(float4*)(yp)     = make_float4(v[0], v[1], v[2], v[3]);
            *(float4*)(yp + 4) = make_float4(v[4], v[5], v[6], v[7]);
        } else {
#pragma unroll
            for (int j = 0; j < 8; j++) {
                int p = P0 + p_start + j;
                y[((size_t)b * 5376 + row_off + p) * 85 + co_off + co] = v[j];
            }
        }
    }
}

extern "C" void kernel_launch(void* const* d_in, const int* in_sizes, int n_in,
                              void* d_out, int out_size)
{
    // metadata order: feat_p3, feat_p4, feat_p5, stem_cls_w, stem_cls_b,
    //                 stem_box_w, stem_box_b, pred_cls_w, pred_cls_b,
    //                 pred_box_w, pred_box_b, pred_ctr_w, pred_ctr_b
    const float* f[13];
    for (int i = 0; i < 13; i++) f[i] = (const float*)d_in[i];
    float* out = (float*)d_out;

    float *A, *B, *W5, *B5;
    cudaGetSymbolAddress((void**)&A,  g_bufA);
    cudaGetSymbolAddress((void**)&B,  g_bufB);
    cudaGetSymbolAddress((void**)&W5, g_w5);
    cudaGetSymbolAddress((void**)&B5, g_b5);

    // fuse box(4) + ctr(1) pred weights into one 5-channel conv
    pack5_kernel<<<(5 * 256 * 9 + 255) / 256, 256>>>(f[9], f[10], f[11], f[12]);

    struct Lv { const float* feat; int H, W, row_off; };
    const Lv lvls[3] = { { f[0], 64, 64, 0 },
                         { f[1], 32, 32, 4096 },
                         { f[2], 16, 16, 5120 } };

    const size_t WSTEM = (size_t)CIN * CIN * 9;  // one stem conv's weights
    for (int l = 0; l < 3; l++) {
        const Lv& L = lvls[l];
        const int HW = L.H * L.W;
        dim3 gs(HW / PXT, (256 + COT - 1) / COT, 16);   // stem grids
        dim3 gc(HW / PXT, (80 + COT - 1) / COT, 16);    // cls pred grid
        dim3 g5(HW / PXT, 1, 16);                       // box+ctr pred grid

        // ---- cls branch: feat -> A -> B -> A -> B -> out[:, :, 0:80]
        conv3x3_kernel<true, false><<<gs, 256>>>(L.feat, f[3] + 0 * WSTEM, f[4] + 0 * 256, A, 256, L.H, L.W, 0, 0);
        conv3x3_kernel<true, false><<<gs, 256>>>(A,      f[3] + 1 * WSTEM, f[4] + 1 * 256, B, 256, L.H, L.W, 0, 0);
        conv3x3_kernel<true, false><<<gs, 256>>>(B,      f[3] + 2 * WSTEM, f[4] + 2 * 256, A, 256, L.H, L.W, 0, 0);
        conv3x3_kernel<true, false><<<gs, 256>>>(A,      f[3] + 3 * WSTEM, f[4] + 3 * 256, B, 256, L.H, L.W, 0, 0);
        conv3x3_kernel<false, true><<<gc, 256>>>(B, f[7], f[8], out, 80, L.H, L.W, L.row_off, 0);

        // ---- box branch: feat -> A -> B -> A -> B -> out[:, :, 80:85]
        conv3x3_kernel<true, false><<<gs, 256>>>(L.feat, f[5] + 0 * WSTEM, f[6] + 0 * 256, A, 256, L.H, L.W, 0, 0);
        conv3x3_kernel<true, false><<<gs, 256>>>(A,      f[5] + 1 * WSTEM, f[6] + 1 * 256, B, 256, L.H, L.W, 0, 0);
        conv3x3_kernel<true, false><<<gs, 256>>>(B,      f[5] + 2 * WSTEM, f[6] + 2 * 256, A, 256, L.H, L.W, 0, 0);
        conv3x3_kernel<true, false><<<gs, 256>>>(A,      f[5] + 3 * WSTEM, f[6] + 3 * 256, B, 256, L.H, L.W, 0, 0);
        conv3x3_kernel<false, true><<<g5, 256>>>(B, W5, B5, out, 5, L.H, L.W, L.row_off, 80);
    }
}